// round 3
// baseline (speedup 1.0000x reference)
#include <cuda_runtime.h>
#include <math.h>
#include <stdint.h>

#define DIM 768
#define TOPK 5
#define COS_EPS 1e-8f
#define W_EPS 1e-6f

#define NBLOCKS 1184      // 148 SMs * 8 blocks (one full wave at 256 thr)
#define NTHREADS 256      // 8 warps
#define NWARPS (NTHREADS / 32)
#define NCAND (NBLOCKS * TOPK)   // 5920

// candidate keys: (monotone dist bits << 32) | row index
__device__ unsigned long long g_cand[NCAND];

__device__ __forceinline__ unsigned int f2u_mono(float f) {
    unsigned int b = __float_as_uint(f);
    return b ^ ((unsigned int)(((int)b) >> 31) | 0x80000000u);
}
__device__ __forceinline__ float u2f_mono(unsigned int u) {
    unsigned int b = (u & 0x80000000u) ? (u ^ 0x80000000u) : ~u;
    return __uint_as_float(b);
}

__device__ __forceinline__ void insert5(unsigned long long best[TOPK],
                                        unsigned long long key) {
    if (key < best[TOPK - 1]) {
        best[TOPK - 1] = key;
        #pragma unroll
        for (int k = TOPK - 1; k > 0; k--) {
            if (best[k] < best[k - 1]) {
                unsigned long long t = best[k];
                best[k] = best[k - 1];
                best[k - 1] = t;
            }
        }
    }
}

// ---------------- kernel 1: fused cosine-distance + per-block top-5 ----------------
// Block-contiguous row range; warps round-robin inside (16 consecutive rows /
// block iteration = 48 KB contiguous streaming front per block).
__global__ void __launch_bounds__(NTHREADS)
dist_topk_kernel(const float* __restrict__ db, const float* __restrict__ q, int n) {
    __shared__ __align__(16) float sq[DIM];
    __shared__ float s_wss[NWARPS];
    __shared__ float s_qn;
    __shared__ unsigned long long s_cand[NWARPS * TOPK];

    const int tid  = threadIdx.x;
    const int lane = tid & 31;
    const int wid  = tid >> 5;

    // load query into shared + compute query norm (redundantly per block; cheap)
    float ss = 0.f;
    for (int i = tid; i < DIM; i += NTHREADS) {
        float v = q[i];
        sq[i] = v;
        ss += v * v;
    }
    #pragma unroll
    for (int o = 16; o; o >>= 1) ss += __shfl_xor_sync(0xFFFFFFFFu, ss, o);
    if (lane == 0) s_wss[wid] = ss;
    __syncthreads();
    if (tid == 0) {
        float t = 0.f;
        #pragma unroll
        for (int i = 0; i < NWARPS; i++) t += s_wss[i];
        s_qn = fmaxf(sqrtf(t), COS_EPS);
    }
    __syncthreads();
    const float qn = s_qn;
    const float4* qv4 = (const float4*)sq;

    // contiguous row range for this BLOCK; warps interleaved by 2 rows
    const int rpb   = (n + NBLOCKS - 1) / NBLOCKS;
    const int bstart = blockIdx.x * rpb;
    const int bend   = min(bstart + rpb, n);

    unsigned long long best[TOPK];
    #pragma unroll
    for (int k = 0; k < TOPK; k++) best[k] = ~0ULL;

    for (int row = bstart + wid * 2; row < bend; row += NWARPS * 2) {
        const bool two = (row + 1 < bend);
        const float4* r0 = (const float4*)(db + (size_t)row * DIM);
        const float4* r1 = two ? (const float4*)(db + (size_t)(row + 1) * DIM) : r0;

        float dot0 = 0.f, nrm0 = 0.f, dot1 = 0.f, nrm1 = 0.f;
        #pragma unroll
        for (int j = 0; j < DIM / (32 * 4); j++) {
            float4 a = __ldcs(&r0[lane + 32 * j]);
            float4 b = __ldcs(&r1[lane + 32 * j]);
            float4 qv = qv4[lane + 32 * j];
            dot0 += a.x * qv.x + a.y * qv.y + a.z * qv.z + a.w * qv.w;
            nrm0 += a.x * a.x + a.y * a.y + a.z * a.z + a.w * a.w;
            dot1 += b.x * qv.x + b.y * qv.y + b.z * qv.z + b.w * qv.w;
            nrm1 += b.x * b.x + b.y * b.y + b.z * b.z + b.w * b.w;
        }
        #pragma unroll
        for (int o = 16; o; o >>= 1) {
            dot0 += __shfl_xor_sync(0xFFFFFFFFu, dot0, o);
            nrm0 += __shfl_xor_sync(0xFFFFFFFFu, nrm0, o);
            dot1 += __shfl_xor_sync(0xFFFFFFFFu, dot1, o);
            nrm1 += __shfl_xor_sync(0xFFFFFFFFu, nrm1, o);
        }
        if (lane == 0) {
            float d0 = 1.f - dot0 / (fmaxf(sqrtf(nrm0), COS_EPS) * qn);
            insert5(best, ((unsigned long long)f2u_mono(d0) << 32) | (unsigned int)row);
            if (two) {
                float d1 = 1.f - dot1 / (fmaxf(sqrtf(nrm1), COS_EPS) * qn);
                insert5(best, ((unsigned long long)f2u_mono(d1) << 32) | (unsigned int)(row + 1));
            }
        }
    }

    // block merge: 8 warps * 5 keys -> 5 keys
    if (lane == 0) {
        #pragma unroll
        for (int k = 0; k < TOPK; k++) s_cand[wid * TOPK + k] = best[k];
    }
    __syncthreads();
    if (tid == 0) {
        const int m = NWARPS * TOPK;  // 40
        #pragma unroll
        for (int k = 0; k < TOPK; k++) {
            unsigned long long mn = ~0ULL;
            int mi = 0;
            for (int i = 0; i < m; i++) {
                unsigned long long v = s_cand[i];
                if (v < mn) { mn = v; mi = i; }
            }
            g_cand[blockIdx.x * TOPK + k] = mn;
            s_cand[mi] = ~0ULL;
        }
    }
}

// ---------------- kernel 2: global top-5 + weighted centroid ----------------
// 1024 threads; stage all candidates into shared ONCE, then 5 in-shared argmin
// passes (clear the winning slot, keys are unique), then centroid gather.
#define FTHREADS 1024
__global__ void __launch_bounds__(FTHREADS)
finish_kernel(const float* __restrict__ db, float* __restrict__ out) {
    __shared__ unsigned long long s_cand[NCAND];  // 47360 B
    __shared__ unsigned long long red[32];
    __shared__ unsigned long long sel[TOPK];
    __shared__ float w[TOPK];
    __shared__ int   id[TOPK];

    const int tid  = threadIdx.x;
    const int lane = tid & 31;
    const int wid  = tid >> 5;

    // coalesced one-shot staging (L2 -> shared)
    for (int i = tid; i < NCAND; i += FTHREADS) s_cand[i] = g_cand[i];
    __syncthreads();

    #pragma unroll
    for (int k = 0; k < TOPK; k++) {
        unsigned long long bst = ~0ULL;
        for (int i = tid; i < NCAND; i += FTHREADS) {
            unsigned long long v = s_cand[i];
            if (v < bst) bst = v;
        }
        #pragma unroll
        for (int o = 16; o; o >>= 1) {
            unsigned long long v = __shfl_xor_sync(0xFFFFFFFFu, bst, o);
            if (v < bst) bst = v;
        }
        if (lane == 0) red[wid] = bst;
        __syncthreads();
        if (tid < 32) {
            unsigned long long v = red[tid];
            #pragma unroll
            for (int o = 16; o; o >>= 1) {
                unsigned long long u = __shfl_xor_sync(0xFFFFFFFFu, v, o);
                if (u < v) v = u;
            }
            if (tid == 0) sel[k] = v;
        }
        __syncthreads();
        // clear the winning slot (keys unique: idx embedded in low bits)
        unsigned long long win = sel[k];
        for (int i = tid; i < NCAND; i += FTHREADS)
            if (s_cand[i] == win) s_cand[i] = ~0ULL;
        __syncthreads();
    }

    if (tid == 0) {
        float raw[TOPK], s = 0.f;
        #pragma unroll
        for (int k = 0; k < TOPK; k++) {
            float d = u2f_mono((unsigned int)(sel[k] >> 32)) + W_EPS;
            raw[k] = 1.f / (d * d);
            s += raw[k];
            id[k] = (int)(unsigned int)(sel[k] & 0xFFFFFFFFu);
        }
        #pragma unroll
        for (int k = 0; k < TOPK; k++) w[k] = raw[k] / s;
    }
    __syncthreads();

    if (tid < DIM) {
        float acc = 0.f;
        #pragma unroll
        for (int k = 0; k < TOPK; k++)
            acc += w[k] * db[(size_t)id[k] * DIM + tid];
        out[tid] = acc;
    }
}

extern "C" void kernel_launch(void* const* d_in, const int* in_sizes, int n_in,
                              void* d_out, int out_size) {
    const float* q  = (const float*)d_in[0];
    const float* db = (const float*)d_in[1];
    float* out = (float*)d_out;
    const int n = in_sizes[1] / DIM;

    dist_topk_kernel<<<NBLOCKS, NTHREADS>>>(db, q, n);
    finish_kernel<<<1, FTHREADS>>>(db, out);
}